// round 14
// baseline (speedup 1.0000x reference)
#include <cuda_runtime.h>
#include <cuda_fp16.h>
#include <cstdint>

#define N_NODES 100000
#define N_EDGES 1600000
#define SCAN_BLOCKS 98   // ceil(100000/1024)

// ====================== helpers =============================================
__device__ __forceinline__ void mma_f16(float c[4], const uint32_t a[4], const uint32_t b[2]) {
    asm volatile(
        "mma.sync.aligned.m16n8k16.row.col.f32.f16.f16.f32 "
        "{%0,%1,%2,%3}, {%4,%5,%6,%7}, {%8,%9}, {%0,%1,%2,%3};"
        : "+f"(c[0]), "+f"(c[1]), "+f"(c[2]), "+f"(c[3])
        : "r"(a[0]), "r"(a[1]), "r"(a[2]), "r"(a[3]), "r"(b[0]), "r"(b[1]));
}
__device__ __forceinline__ uint32_t pack_h2(float a, float b) {
    __half2 h = __floats2half2_rn(a, b);
    return *(uint32_t*)&h;
}

// ====================== scratch globals =====================================
__device__ __half g_ylh[(size_t)N_NODES * 128];  // yl (fp16, gathered side)
__device__ float  g_yr[(size_t)N_NODES * 128];   // yr (fp32, exact side)
__device__ __half g_act[(size_t)N_NODES * 128];  // fp16 activations (h1 / g)
__device__ int    g_deg[N_NODES];
__device__ int    g_fill[N_NODES];
__device__ int    g_rowptr[N_NODES + 1];
__device__ int    g_csr[N_EDGES];
__device__ int    g_bsums[SCAN_BLOCKS];
__device__ int    g_nbin[256];        // degree-bucket histogram
__device__ int    g_nbinstart[256];   // exclusive starts
__device__ int    g_nbinfill[256];    // scatter cursors
__device__ int    g_order[N_NODES];   // nodes sorted by degree
__device__ float  g_wt0[256 * 256];   // [n][k]: n<128 -> Wl0[:,n], else Wr0[:,n-128]
__device__ float  g_wt1[256 * 128];
__device__ float  g_wt2[128 * 128];

// ====================== CSR build + degree sort =============================
__global__ void zero_kernel() {
    int i = blockIdx.x * blockDim.x + threadIdx.x;
    if (i < N_NODES) { g_deg[i] = 0; g_fill[i] = 0; }
    if (i < 256) { g_nbin[i] = 0; g_nbinfill[i] = 0; }
}
__global__ void deg_kernel(const int* __restrict__ dst) {
    int e = blockIdx.x * blockDim.x + threadIdx.x;
    if (e < N_EDGES) atomicAdd(&g_deg[dst[e]], 1);
}
__global__ void scan1_kernel() {
    __shared__ int s[1024];
    int tid = threadIdx.x;
    int idx = blockIdx.x * 1024 + tid;
    int v = (idx < N_NODES) ? g_deg[idx] : 0;
    s[tid] = v;
    __syncthreads();
    for (int off = 1; off < 1024; off <<= 1) {
        int t = 0;
        if (tid >= off) t = s[tid - off];
        __syncthreads();
        s[tid] += t;
        __syncthreads();
    }
    if (idx < N_NODES) g_rowptr[idx + 1] = s[tid];
    if (tid == 1023) g_bsums[blockIdx.x] = s[tid];
    if (idx == 0) g_rowptr[0] = 0;
}
__global__ void scan2_kernel() {       // 128-thread shfl scan over SCAN_BLOCKS sums
    int tid = threadIdx.x;
    int v = (tid < SCAN_BLOCKS) ? g_bsums[tid] : 0;
    int lane = tid & 31, w = tid >> 5;
    int x = v;
    for (int o = 1; o < 32; o <<= 1) {
        int t = __shfl_up_sync(0xFFFFFFFFu, x, o);
        if (lane >= o) x += t;
    }
    __shared__ int ws[4];
    if (lane == 31) ws[w] = x;
    __syncthreads();
    int add = 0;
    for (int i = 0; i < w; i++) add += ws[i];
    if (tid < SCAN_BLOCKS) g_bsums[tid] = x + add - v;  // exclusive
}
__global__ void scan3_kernel() {
    int idx = blockIdx.x * 1024 + threadIdx.x;
    if (idx < N_NODES) g_rowptr[idx + 1] += g_bsums[blockIdx.x];
}
__global__ void fill_kernel(const int* __restrict__ src, const int* __restrict__ dst) {
    int e = blockIdx.x * blockDim.x + threadIdx.x;
    if (e < N_EDGES) {
        int d = dst[e];
        int pos = g_rowptr[d] + atomicAdd(&g_fill[d], 1);
        g_csr[pos] = src[e];
    }
}
__global__ void hist_kernel() {
    int i = blockIdx.x * blockDim.x + threadIdx.x;
    if (i < N_NODES) atomicAdd(&g_nbin[min(g_deg[i], 255)], 1);
}
__global__ void scanbins_kernel() {    // 256 threads, exclusive scan of g_nbin
    int tid = threadIdx.x;
    int v = g_nbin[tid];
    int lane = tid & 31, w = tid >> 5;
    int x = v;
    for (int o = 1; o < 32; o <<= 1) {
        int t = __shfl_up_sync(0xFFFFFFFFu, x, o);
        if (lane >= o) x += t;
    }
    __shared__ int ws[8];
    if (lane == 31) ws[w] = x;
    __syncthreads();
    int add = 0;
    for (int i = 0; i < w; i++) add += ws[i];
    g_nbinstart[tid] = x + add - v;    // exclusive
}
__global__ void scatter_kernel() {
    int i = blockIdx.x * blockDim.x + threadIdx.x;
    if (i < N_NODES) {
        int b = min(g_deg[i], 255);
        int pos = g_nbinstart[b] + atomicAdd(&g_nbinfill[b], 1);
        g_order[pos] = i;
    }
}

// ====================== weight pre-transpose ================================
__global__ void wtrans_kernel(const float* __restrict__ Wl0, const float* __restrict__ Wr0,
                              const float* __restrict__ Wl1, const float* __restrict__ Wr1,
                              const float* __restrict__ Wl2, const float* __restrict__ Wr2) {
    int i = blockIdx.x * blockDim.x + threadIdx.x;
    if (i < 256 * 256) {                       // wt0: N=256, K=256
        int n = i >> 8, k = i & 255;
        g_wt0[i] = (n < 128) ? Wl0[k * 128 + n] : Wr0[k * 128 + (n - 128)];
    }
    if (i < 256 * 128) {                       // wt1: N=256, K=128
        int n = i >> 7, k = i & 127;
        g_wt1[i] = (n < 128) ? Wl1[k * 128 + n] : Wr1[k * 128 + (n - 128)];
    }
    if (i < 128 * 128) {                       // wt2: N=128, K=128
        int n = i >> 7, k = i & 127;
        g_wt2[i] = (n < 64) ? Wl2[k * 64 + n] : Wr2[k * 64 + (n - 64)];
    }
}

// ====================== mma.sync fp16 GEMM (R10 proven) =====================
// Y[M, NN] = A[M, KT] * BT[NN, KT]^T, cols [0,SPLIT) -> fp16 ylh, rest -> fp32 yr.
#define KC 32
#define SH 40                              // halves per row; rows hit distinct banks
#define BUF_H (128 * SH)
#define STAGE_H (2 * BUF_H)

template <int KT, int NN, typename TA>
__global__ void __launch_bounds__(256)
gemm_mma_kernel(const TA* __restrict__ A, const float* __restrict__ BT,
                __half* __restrict__ ylh, float* __restrict__ yr, int M) {
    constexpr int SPLIT = NN / 2;
    constexpr bool A_IS_HALF = sizeof(TA) == 2;
    __shared__ __half sm[2 * STAGE_H];     // 40960 bytes
    const int tid = threadIdx.x;
    const int wid = tid >> 5;
    const int lane = tid & 31;
    const int warpM = wid & 3;
    const int warpN = wid >> 2;
    const int rowBase = blockIdx.x * 128;
    const int colBase = blockIdx.y * 128;
    constexpr int NC = KT / KC;

    float acc[2][8][4];
#pragma unroll
    for (int mt = 0; mt < 2; mt++)
#pragma unroll
        for (int nt = 0; nt < 8; nt++)
#pragma unroll
            for (int q = 0; q < 4; q++) acc[mt][nt][q] = 0.f;

    const int ldRow = tid >> 3;          // 0..31 (+i*32)
    const int ldKq  = (tid & 7) * 4;     // k offset (elements)

    uint2 ha[4];       // fp16 A path
    float4 ra[4];      // fp32 A path
    float4 rb[4];

    auto loadA = [&](int kBase) {
#pragma unroll
        for (int i = 0; i < 4; i++) {
            int gr = rowBase + ldRow + i * 32;
            if (A_IS_HALF) {
                ha[i] = (gr < M) ? *(const uint2*)((const __half*)A + (size_t)gr * KT + kBase + ldKq)
                                 : make_uint2(0u, 0u);
            } else {
                ra[i] = (gr < M) ? *(const float4*)((const float*)A + (size_t)gr * KT + kBase + ldKq)
                                 : make_float4(0.f, 0.f, 0.f, 0.f);
            }
        }
    };
    auto loadB = [&](int kBase) {
#pragma unroll
        for (int i = 0; i < 4; i++)
            rb[i] = *(const float4*)(BT + (size_t)(colBase + ldRow + i * 32) * KT + kBase + ldKq);
    };
    auto storeStage = [&](int stg) {
        __half* As = sm + stg * STAGE_H;
        __half* Bs = As + BUF_H;
#pragma unroll
        for (int i = 0; i < 4; i++) {
            int r = ldRow + i * 32;
            if (A_IS_HALF) {
                *(uint2*)(As + r * SH + ldKq) = ha[i];
            } else {
                *(uint2*)(As + r * SH + ldKq) = make_uint2(pack_h2(ra[i].x, ra[i].y),
                                                           pack_h2(ra[i].z, ra[i].w));
            }
            *(uint2*)(Bs + r * SH + ldKq) = make_uint2(pack_h2(rb[i].x, rb[i].y),
                                                       pack_h2(rb[i].z, rb[i].w));
        }
    };

    loadA(0); loadB(0); storeStage(0);
    __syncthreads();

    const int aRowB = warpM * 32 + (lane >> 2);
    const int aCol2 = (lane & 3) * 2;
    const int bRowB = warpN * 64 + (lane >> 2);

    for (int c = 0; c < NC; c++) {
        if (c + 1 < NC) { loadA((c + 1) * KC); loadB((c + 1) * KC); }
        const __half* As = sm + (c & 1) * STAGE_H;
        const __half* Bs = As + BUF_H;
#pragma unroll
        for (int ks = 0; ks < KC / 16; ks++) {
            const int k0 = ks * 16 + aCol2;
            uint32_t af[2][4];
            uint32_t bf[8][2];
#pragma unroll
            for (int mt = 0; mt < 2; mt++) {
                const __half* p = As + (aRowB + mt * 16) * SH + k0;
                af[mt][0] = *(const uint32_t*)(p);
                af[mt][1] = *(const uint32_t*)(p + 8 * SH);
                af[mt][2] = *(const uint32_t*)(p + 8);
                af[mt][3] = *(const uint32_t*)(p + 8 * SH + 8);
            }
#pragma unroll
            for (int nt = 0; nt < 8; nt++) {
                const __half* p = Bs + (bRowB + nt * 8) * SH + k0;
                bf[nt][0] = *(const uint32_t*)(p);
                bf[nt][1] = *(const uint32_t*)(p + 8);
            }
#pragma unroll
            for (int mt = 0; mt < 2; mt++)
#pragma unroll
                for (int nt = 0; nt < 8; nt++)
                    mma_f16(acc[mt][nt], af[mt], bf[nt]);
        }
        if (c + 1 < NC) {
            storeStage((c + 1) & 1);
            __syncthreads();
        }
    }

    // ---- epilogue: split write (fp16 yl / fp32 yr) ----
#pragma unroll
    for (int mt = 0; mt < 2; mt++) {
        int r0 = rowBase + warpM * 32 + mt * 16 + (lane >> 2);
#pragma unroll
        for (int nt = 0; nt < 8; nt++) {
            int colg = colBase + warpN * 64 + nt * 8 + (lane & 3) * 2;
#pragma unroll
            for (int hf = 0; hf < 2; hf++) {
                int row = r0 + hf * 8;
                if (row >= M) continue;
                float c0 = acc[mt][nt][hf * 2 + 0];
                float c1 = acc[mt][nt][hf * 2 + 1];
                if (colg < SPLIT) {
                    *(__half2*)(ylh + (size_t)row * SPLIT + colg) = __floats2half2_rn(c0, c1);
                } else {
                    *(float2*)(yr + (size_t)row * SPLIT + (colg - SPLIT)) = make_float2(c0, c1);
                }
            }
        }
    }
}

// ====================== aggregation epilogue (degree-sorted) ================
// One warp per sorted slot; node = g_order[slot]. Lane covers 4 channels.
template <bool WPRE32, bool WPOST32, bool WPOST16>
__global__ void agg128_kernel(const __half* __restrict__ yl, const float* __restrict__ yr,
                              const float* __restrict__ bias,
                              float* __restrict__ outPre, float* __restrict__ outPost,
                              __half* __restrict__ outPost16) {
    int slot = (blockIdx.x * blockDim.x + threadIdx.x) >> 5;
    int lane = threadIdx.x & 31;
    if (slot >= N_NODES) return;
    int node = g_order[slot];
    int beg = g_rowptr[node], end = g_rowptr[node + 1];
    float ax = 0.f, ay = 0.f, az = 0.f, aw = 0.f;
    int e = beg;
    for (; e + 4 <= end; e += 4) {
        int s0 = g_csr[e], s1 = g_csr[e + 1], s2 = g_csr[e + 2], s3 = g_csr[e + 3];
        uint2 q0 = *(const uint2*)(yl + (size_t)s0 * 128 + lane * 4);
        uint2 q1 = *(const uint2*)(yl + (size_t)s1 * 128 + lane * 4);
        uint2 q2 = *(const uint2*)(yl + (size_t)s2 * 128 + lane * 4);
        uint2 q3 = *(const uint2*)(yl + (size_t)s3 * 128 + lane * 4);
        float2 a0 = __half22float2(*(__half2*)&q0.x), b0 = __half22float2(*(__half2*)&q0.y);
        float2 a1 = __half22float2(*(__half2*)&q1.x), b1 = __half22float2(*(__half2*)&q1.y);
        float2 a2 = __half22float2(*(__half2*)&q2.x), b2 = __half22float2(*(__half2*)&q2.y);
        float2 a3 = __half22float2(*(__half2*)&q3.x), b3 = __half22float2(*(__half2*)&q3.y);
        ax += a0.x + a1.x + a2.x + a3.x;
        ay += a0.y + a1.y + a2.y + a3.y;
        az += b0.x + b1.x + b2.x + b3.x;
        aw += b0.y + b1.y + b2.y + b3.y;
    }
    for (; e < end; e++) {
        int s = g_csr[e];
        uint2 q = *(const uint2*)(yl + (size_t)s * 128 + lane * 4);
        float2 a = __half22float2(*(__half2*)&q.x), b = __half22float2(*(__half2*)&q.y);
        ax += a.x; ay += a.y; az += b.x; aw += b.y;
    }
    int deg = end - beg;
    float inv = 1.f / (float)(deg > 0 ? deg : 1);
    float4 r = *(const float4*)(yr + (size_t)node * 128 + lane * 4);
    float4 b = *(const float4*)(bias + lane * 4);
    float v0 = ax * inv + r.x + b.x;
    float v1 = ay * inv + r.y + b.y;
    float v2 = az * inv + r.z + b.z;
    float v3 = aw * inv + r.w + b.w;
    size_t o = (size_t)node * 128 + lane * 4;
    if (WPRE32)  *(float4*)(outPre + o) = make_float4(v0, v1, v2, v3);
    float p0 = fmaxf(v0, 0.f), p1 = fmaxf(v1, 0.f), p2 = fmaxf(v2, 0.f), p3 = fmaxf(v3, 0.f);
    if (WPOST32) *(float4*)(outPost + o) = make_float4(p0, p1, p2, p3);
    if (WPOST16) *(uint2*)(outPost16 + o) = make_uint2(pack_h2(p0, p1), pack_h2(p2, p3));
}

__global__ void agg64_kernel(const __half* __restrict__ yl, const float* __restrict__ yr,
                             const float* __restrict__ bias, float* __restrict__ outPre) {
    int slot = (blockIdx.x * blockDim.x + threadIdx.x) >> 5;
    int lane = threadIdx.x & 31;
    if (slot >= N_NODES) return;
    int node = g_order[slot];
    int beg = g_rowptr[node], end = g_rowptr[node + 1];
    float ax = 0.f, ay = 0.f;
    int e = beg;
    for (; e + 4 <= end; e += 4) {
        int s0 = g_csr[e], s1 = g_csr[e + 1], s2 = g_csr[e + 2], s3 = g_csr[e + 3];
        uint32_t q0 = *(const uint32_t*)(yl + (size_t)s0 * 64 + lane * 2);
        uint32_t q1 = *(const uint32_t*)(yl + (size_t)s1 * 64 + lane * 2);
        uint32_t q2 = *(const uint32_t*)(yl + (size_t)s2 * 64 + lane * 2);
        uint32_t q3 = *(const uint32_t*)(yl + (size_t)s3 * 64 + lane * 2);
        float2 a0 = __half22float2(*(__half2*)&q0);
        float2 a1 = __half22float2(*(__half2*)&q1);
        float2 a2 = __half22float2(*(__half2*)&q2);
        float2 a3 = __half22float2(*(__half2*)&q3);
        ax += a0.x + a1.x + a2.x + a3.x;
        ay += a0.y + a1.y + a2.y + a3.y;
    }
    for (; e < end; e++) {
        int s = g_csr[e];
        uint32_t q = *(const uint32_t*)(yl + (size_t)s * 64 + lane * 2);
        float2 a = __half22float2(*(__half2*)&q);
        ax += a.x; ay += a.y;
    }
    int deg = end - beg;
    float inv = 1.f / (float)(deg > 0 ? deg : 1);
    float2 r = *(const float2*)(yr + (size_t)node * 64 + lane * 2);
    float2 b = *(const float2*)(bias + lane * 2);
    float v0 = ax * inv + r.x + b.x;
    float v1 = ay * inv + r.y + b.y;
    *(float2*)(outPre + (size_t)node * 64 + lane * 2) = make_float2(v0, v1);
}

// ====================== host launch =========================================
extern "C" void kernel_launch(void* const* d_in, const int* in_sizes, int n_in,
                              void* d_out, int out_size) {
    const float* x   = (const float*)d_in[0];
    const int*   ei  = (const int*)d_in[1];
    const float* Wl0 = (const float*)d_in[2];
    const float* Wr0 = (const float*)d_in[3];
    const float* b0  = (const float*)d_in[4];
    const float* Wl1 = (const float*)d_in[5];
    const float* Wr1 = (const float*)d_in[6];
    const float* b1  = (const float*)d_in[7];
    const float* Wl2 = (const float*)d_in[8];
    const float* Wr2 = (const float*)d_in[9];
    const float* b2  = (const float*)d_in[10];

    const int* src = ei;
    const int* dst = ei + N_EDGES;

    float* out_final = (float*)d_out;                       // [N,64]
    float* out_pre1  = out_final + (size_t)N_NODES * 64;    // [N,128] pre-relu layer1
    float* out_g     = out_pre1 + (size_t)N_NODES * 128;    // [N,128] relu(layer1)

    __half *ylh, *actp; float *yrp, *wt0, *wt1, *wt2;
    cudaGetSymbolAddress((void**)&ylh, g_ylh);
    cudaGetSymbolAddress((void**)&actp, g_act);
    cudaGetSymbolAddress((void**)&yrp, g_yr);
    cudaGetSymbolAddress((void**)&wt0, g_wt0);
    cudaGetSymbolAddress((void**)&wt1, g_wt1);
    cudaGetSymbolAddress((void**)&wt2, g_wt2);

    static cudaStream_t s_side = nullptr;
    static cudaEvent_t evFork = nullptr, evJoin = nullptr;
    if (s_side == nullptr) {
        cudaStreamCreateWithFlags(&s_side, cudaStreamNonBlocking);
        cudaEventCreateWithFlags(&evFork, cudaEventDisableTiming);
        cudaEventCreateWithFlags(&evJoin, cudaEventDisableTiming);
    }

    // ---- fork: CSR build + degree sort on side stream ----
    cudaEventRecord(evFork, 0);
    cudaStreamWaitEvent(s_side, evFork, 0);
    zero_kernel<<<(N_NODES + 1023) / 1024, 1024, 0, s_side>>>();
    deg_kernel<<<(N_EDGES + 255) / 256, 256, 0, s_side>>>(dst);
    scan1_kernel<<<SCAN_BLOCKS, 1024, 0, s_side>>>();
    scan2_kernel<<<1, 128, 0, s_side>>>();
    scan3_kernel<<<SCAN_BLOCKS, 1024, 0, s_side>>>();
    fill_kernel<<<(N_EDGES + 255) / 256, 256, 0, s_side>>>(src, dst);
    hist_kernel<<<(N_NODES + 255) / 256, 256, 0, s_side>>>();
    scanbins_kernel<<<1, 256, 0, s_side>>>();
    scatter_kernel<<<(N_NODES + 255) / 256, 256, 0, s_side>>>();
    cudaEventRecord(evJoin, s_side);

    // ---- main stream overlaps the CSR build ----
    wtrans_kernel<<<(256 * 256 + 255) / 256, 256>>>(Wl0, Wr0, Wl1, Wr1, Wl2, Wr2);

    const int aggGrid = (N_NODES * 32 + 255) / 256;
    const int gemmGridX = (N_NODES + 127) / 128;   // 782

    // Layer 0: [yl|yr] = x@[Wl0|Wr0]; h1(fp16) = relu(mean(yl) + yr + b0)
    gemm_mma_kernel<256, 256, float><<<dim3(gemmGridX, 2), 256>>>(x, wt0, ylh, yrp, N_NODES);
    cudaStreamWaitEvent(0, evJoin, 0);   // agg needs the CSR + order
    agg128_kernel<false, false, true><<<aggGrid, 256>>>(ylh, yrp, b0, nullptr, nullptr, actp);

    // Layer 1: out_pre1 = mean+yr+b1; g -> out_g (fp32) + g_act (fp16)
    gemm_mma_kernel<128, 256, __half><<<dim3(gemmGridX, 2), 256>>>(actp, wt1, ylh, yrp, N_NODES);
    agg128_kernel<true, true, true><<<aggGrid, 256>>>(ylh, yrp, b1, out_pre1, out_g, actp);

    // Layer 2: x_final = mean(yl) + yr + b2 (no relu)
    gemm_mma_kernel<128, 128, __half><<<dim3(gemmGridX, 1), 256>>>(actp, wt2, ylh, yrp, N_NODES);
    agg64_kernel<<<aggGrid, 256>>>(ylh, yrp, b2, out_final);
}

// round 16
// speedup vs baseline: 1.0297x; 1.0297x over previous
#include <cuda_runtime.h>
#include <cuda_fp16.h>
#include <cstdint>

#define N_NODES 100000
#define N_EDGES 1600000
#define SCAN_BLOCKS 98   // ceil(100000/1024)
#define NCHUNKS 4
#define CHUNK 25088      // multiple of 128; last chunk = 24736

// ====================== helpers =============================================
__device__ __forceinline__ void mma_f16(float c[4], const uint32_t a[4], const uint32_t b[2]) {
    asm volatile(
        "mma.sync.aligned.m16n8k16.row.col.f32.f16.f16.f32 "
        "{%0,%1,%2,%3}, {%4,%5,%6,%7}, {%8,%9}, {%0,%1,%2,%3};"
        : "+f"(c[0]), "+f"(c[1]), "+f"(c[2]), "+f"(c[3])
        : "r"(a[0]), "r"(a[1]), "r"(a[2]), "r"(a[3]), "r"(b[0]), "r"(b[1]));
}
__device__ __forceinline__ uint32_t pack_h2(float a, float b) {
    __half2 h = __floats2half2_rn(a, b);
    return *(uint32_t*)&h;
}

// ====================== scratch globals =====================================
// Double-buffered GEMM outputs: set A (layer0, layer2) and set B (layer1).
__device__ __half g_ylhA[(size_t)N_NODES * 128];
__device__ float  g_yrA[(size_t)N_NODES * 128];
__device__ __half g_ylhB[(size_t)N_NODES * 128];
__device__ float  g_yrB[(size_t)N_NODES * 128];
__device__ __half g_act[(size_t)N_NODES * 128];  // fp16 activations (h1 / g)
__device__ int    g_deg[N_NODES];
__device__ int    g_fill[N_NODES];
__device__ int    g_rowptr[N_NODES + 1];
__device__ int    g_csr[N_EDGES];
__device__ int    g_bsums[SCAN_BLOCKS];
__device__ float  g_wt0[256 * 256];   // [n][k]: n<128 -> Wl0[:,n], else Wr0[:,n-128]
__device__ float  g_wt1[256 * 128];
__device__ float  g_wt2[128 * 128];

// ====================== CSR build ===========================================
__global__ void zero_kernel() {
    int i = blockIdx.x * blockDim.x + threadIdx.x;
    if (i < N_NODES) { g_deg[i] = 0; g_fill[i] = 0; }
}
__global__ void deg_kernel(const int* __restrict__ dst) {
    int e = blockIdx.x * blockDim.x + threadIdx.x;
    if (e < N_EDGES) atomicAdd(&g_deg[dst[e]], 1);
}
__global__ void scan1_kernel() {
    __shared__ int s[1024];
    int tid = threadIdx.x;
    int idx = blockIdx.x * 1024 + tid;
    int v = (idx < N_NODES) ? g_deg[idx] : 0;
    s[tid] = v;
    __syncthreads();
    for (int off = 1; off < 1024; off <<= 1) {
        int t = 0;
        if (tid >= off) t = s[tid - off];
        __syncthreads();
        s[tid] += t;
        __syncthreads();
    }
    if (idx < N_NODES) g_rowptr[idx + 1] = s[tid];
    if (tid == 1023) g_bsums[blockIdx.x] = s[tid];
    if (idx == 0) g_rowptr[0] = 0;
}
__global__ void scan2_kernel() {       // 128-thread shfl scan over SCAN_BLOCKS sums
    int tid = threadIdx.x;
    int v = (tid < SCAN_BLOCKS) ? g_bsums[tid] : 0;
    int lane = tid & 31, w = tid >> 5;
    int x = v;
    for (int o = 1; o < 32; o <<= 1) {
        int t = __shfl_up_sync(0xFFFFFFFFu, x, o);
        if (lane >= o) x += t;
    }
    __shared__ int ws[4];
    if (lane == 31) ws[w] = x;
    __syncthreads();
    int add = 0;
    for (int i = 0; i < w; i++) add += ws[i];
    if (tid < SCAN_BLOCKS) g_bsums[tid] = x + add - v;  // exclusive
}
__global__ void scan3_kernel() {
    int idx = blockIdx.x * 1024 + threadIdx.x;
    if (idx < N_NODES) g_rowptr[idx + 1] += g_bsums[blockIdx.x];
}
__global__ void fill_kernel(const int* __restrict__ src, const int* __restrict__ dst) {
    int e = blockIdx.x * blockDim.x + threadIdx.x;
    if (e < N_EDGES) {
        int d = dst[e];
        int pos = g_rowptr[d] + atomicAdd(&g_fill[d], 1);
        g_csr[pos] = src[e];
    }
}

// ====================== weight pre-transpose ================================
__global__ void wtrans_kernel(const float* __restrict__ Wl0, const float* __restrict__ Wr0,
                              const float* __restrict__ Wl1, const float* __restrict__ Wr1,
                              const float* __restrict__ Wl2, const float* __restrict__ Wr2) {
    int i = blockIdx.x * blockDim.x + threadIdx.x;
    if (i < 256 * 256) {                       // wt0: N=256, K=256
        int n = i >> 8, k = i & 255;
        g_wt0[i] = (n < 128) ? Wl0[k * 128 + n] : Wr0[k * 128 + (n - 128)];
    }
    if (i < 256 * 128) {                       // wt1: N=256, K=128
        int n = i >> 7, k = i & 127;
        g_wt1[i] = (n < 128) ? Wl1[k * 128 + n] : Wr1[k * 128 + (n - 128)];
    }
    if (i < 128 * 128) {                       // wt2: N=128, K=128
        int n = i >> 7, k = i & 127;
        g_wt2[i] = (n < 64) ? Wl2[k * 64 + n] : Wr2[k * 64 + (n - 64)];
    }
}

// ====================== mma.sync fp16 GEMM (R10 proven) =====================
// Y[M, NN] = A[M, KT] * BT[NN, KT]^T, cols [0,SPLIT) -> fp16 ylh, rest -> fp32 yr.
#define KC 32
#define SH 40                              // halves per row; rows hit distinct banks
#define BUF_H (128 * SH)
#define STAGE_H (2 * BUF_H)

template <int KT, int NN, typename TA>
__global__ void __launch_bounds__(256)
gemm_mma_kernel(const TA* __restrict__ A, const float* __restrict__ BT,
                __half* __restrict__ ylh, float* __restrict__ yr, int M) {
    constexpr int SPLIT = NN / 2;
    constexpr bool A_IS_HALF = sizeof(TA) == 2;
    __shared__ __half sm[2 * STAGE_H];     // 40960 bytes
    const int tid = threadIdx.x;
    const int wid = tid >> 5;
    const int lane = tid & 31;
    const int warpM = wid & 3;
    const int warpN = wid >> 2;
    const int rowBase = blockIdx.x * 128;
    const int colBase = blockIdx.y * 128;
    constexpr int NC = KT / KC;

    float acc[2][8][4];
#pragma unroll
    for (int mt = 0; mt < 2; mt++)
#pragma unroll
        for (int nt = 0; nt < 8; nt++)
#pragma unroll
            for (int q = 0; q < 4; q++) acc[mt][nt][q] = 0.f;

    const int ldRow = tid >> 3;          // 0..31 (+i*32)
    const int ldKq  = (tid & 7) * 4;     // k offset (elements)

    uint2 ha[4];       // fp16 A path
    float4 ra[4];      // fp32 A path
    float4 rb[4];

    auto loadA = [&](int kBase) {
#pragma unroll
        for (int i = 0; i < 4; i++) {
            int gr = rowBase + ldRow + i * 32;
            if (A_IS_HALF) {
                ha[i] = (gr < M) ? *(const uint2*)((const __half*)A + (size_t)gr * KT + kBase + ldKq)
                                 : make_uint2(0u, 0u);
            } else {
                ra[i] = (gr < M) ? *(const float4*)((const float*)A + (size_t)gr * KT + kBase + ldKq)
                                 : make_float4(0.f, 0.f, 0.f, 0.f);
            }
        }
    };
    auto loadB = [&](int kBase) {
#pragma unroll
        for (int i = 0; i < 4; i++)
            rb[i] = *(const float4*)(BT + (size_t)(colBase + ldRow + i * 32) * KT + kBase + ldKq);
    };
    auto storeStage = [&](int stg) {
        __half* As = sm + stg * STAGE_H;
        __half* Bs = As + BUF_H;
#pragma unroll
        for (int i = 0; i < 4; i++) {
            int r = ldRow + i * 32;
            if (A_IS_HALF) {
                *(uint2*)(As + r * SH + ldKq) = ha[i];
            } else {
                *(uint2*)(As + r * SH + ldKq) = make_uint2(pack_h2(ra[i].x, ra[i].y),
                                                           pack_h2(ra[i].z, ra[i].w));
            }
            *(uint2*)(Bs + r * SH + ldKq) = make_uint2(pack_h2(rb[i].x, rb[i].y),
                                                       pack_h2(rb[i].z, rb[i].w));
        }
    };

    loadA(0); loadB(0); storeStage(0);
    __syncthreads();

    const int aRowB = warpM * 32 + (lane >> 2);
    const int aCol2 = (lane & 3) * 2;
    const int bRowB = warpN * 64 + (lane >> 2);

    for (int c = 0; c < NC; c++) {
        if (c + 1 < NC) { loadA((c + 1) * KC); loadB((c + 1) * KC); }
        const __half* As = sm + (c & 1) * STAGE_H;
        const __half* Bs = As + BUF_H;
#pragma unroll
        for (int ks = 0; ks < KC / 16; ks++) {
            const int k0 = ks * 16 + aCol2;
            uint32_t af[2][4];
            uint32_t bf[8][2];
#pragma unroll
            for (int mt = 0; mt < 2; mt++) {
                const __half* p = As + (aRowB + mt * 16) * SH + k0;
                af[mt][0] = *(const uint32_t*)(p);
                af[mt][1] = *(const uint32_t*)(p + 8 * SH);
                af[mt][2] = *(const uint32_t*)(p + 8);
                af[mt][3] = *(const uint32_t*)(p + 8 * SH + 8);
            }
#pragma unroll
            for (int nt = 0; nt < 8; nt++) {
                const __half* p = Bs + (bRowB + nt * 8) * SH + k0;
                bf[nt][0] = *(const uint32_t*)(p);
                bf[nt][1] = *(const uint32_t*)(p + 8);
            }
#pragma unroll
            for (int mt = 0; mt < 2; mt++)
#pragma unroll
                for (int nt = 0; nt < 8; nt++)
                    mma_f16(acc[mt][nt], af[mt], bf[nt]);
        }
        if (c + 1 < NC) {
            storeStage((c + 1) & 1);
            __syncthreads();
        }
    }

    // ---- epilogue: split write (fp16 yl / fp32 yr) ----
#pragma unroll
    for (int mt = 0; mt < 2; mt++) {
        int r0 = rowBase + warpM * 32 + mt * 16 + (lane >> 2);
#pragma unroll
        for (int nt = 0; nt < 8; nt++) {
            int colg = colBase + warpN * 64 + nt * 8 + (lane & 3) * 2;
#pragma unroll
            for (int hf = 0; hf < 2; hf++) {
                int row = r0 + hf * 8;
                if (row >= M) continue;
                float c0 = acc[mt][nt][hf * 2 + 0];
                float c1 = acc[mt][nt][hf * 2 + 1];
                if (colg < SPLIT) {
                    *(__half2*)(ylh + (size_t)row * SPLIT + colg) = __floats2half2_rn(c0, c1);
                } else {
                    *(float2*)(yr + (size_t)row * SPLIT + (colg - SPLIT)) = make_float2(c0, c1);
                }
            }
        }
    }
}

// ====================== aggregation epilogue (R10 structure + node offset) ==
template <bool WPRE32, bool WPOST32, bool WPOST16>
__global__ void agg128_kernel(const __half* __restrict__ yl, const float* __restrict__ yr,
                              const float* __restrict__ bias,
                              float* __restrict__ outPre, float* __restrict__ outPost,
                              __half* __restrict__ outPost16, int nodeOff, int nNodes) {
    int slot = (blockIdx.x * blockDim.x + threadIdx.x) >> 5;
    int lane = threadIdx.x & 31;
    if (slot >= nNodes) return;
    int node = nodeOff + slot;
    int beg = g_rowptr[node], end = g_rowptr[node + 1];
    float ax = 0.f, ay = 0.f, az = 0.f, aw = 0.f;
    int e = beg;
    for (; e + 4 <= end; e += 4) {
        int s0 = g_csr[e], s1 = g_csr[e + 1], s2 = g_csr[e + 2], s3 = g_csr[e + 3];
        uint2 q0 = *(const uint2*)(yl + (size_t)s0 * 128 + lane * 4);
        uint2 q1 = *(const uint2*)(yl + (size_t)s1 * 128 + lane * 4);
        uint2 q2 = *(const uint2*)(yl + (size_t)s2 * 128 + lane * 4);
        uint2 q3 = *(const uint2*)(yl + (size_t)s3 * 128 + lane * 4);
        float2 a0 = __half22float2(*(__half2*)&q0.x), b0 = __half22float2(*(__half2*)&q0.y);
        float2 a1 = __half22float2(*(__half2*)&q1.x), b1 = __half22float2(*(__half2*)&q1.y);
        float2 a2 = __half22float2(*(__half2*)&q2.x), b2 = __half22float2(*(__half2*)&q2.y);
        float2 a3 = __half22float2(*(__half2*)&q3.x), b3 = __half22float2(*(__half2*)&q3.y);
        ax += a0.x + a1.x + a2.x + a3.x;
        ay += a0.y + a1.y + a2.y + a3.y;
        az += b0.x + b1.x + b2.x + b3.x;
        aw += b0.y + b1.y + b2.y + b3.y;
    }
    for (; e < end; e++) {
        int s = g_csr[e];
        uint2 q = *(const uint2*)(yl + (size_t)s * 128 + lane * 4);
        float2 a = __half22float2(*(__half2*)&q.x), b = __half22float2(*(__half2*)&q.y);
        ax += a.x; ay += a.y; az += b.x; aw += b.y;
    }
    int deg = end - beg;
    float inv = 1.f / (float)(deg > 0 ? deg : 1);
    float4 r = *(const float4*)(yr + (size_t)node * 128 + lane * 4);
    float4 b = *(const float4*)(bias + lane * 4);
    float v0 = ax * inv + r.x + b.x;
    float v1 = ay * inv + r.y + b.y;
    float v2 = az * inv + r.z + b.z;
    float v3 = aw * inv + r.w + b.w;
    size_t o = (size_t)node * 128 + lane * 4;
    if (WPRE32)  *(float4*)(outPre + o) = make_float4(v0, v1, v2, v3);
    float p0 = fmaxf(v0, 0.f), p1 = fmaxf(v1, 0.f), p2 = fmaxf(v2, 0.f), p3 = fmaxf(v3, 0.f);
    if (WPOST32) *(float4*)(outPost + o) = make_float4(p0, p1, p2, p3);
    if (WPOST16) *(uint2*)(outPost16 + o) = make_uint2(pack_h2(p0, p1), pack_h2(p2, p3));
}

__global__ void agg64_kernel(const __half* __restrict__ yl, const float* __restrict__ yr,
                             const float* __restrict__ bias, float* __restrict__ outPre) {
    int warp = (blockIdx.x * blockDim.x + threadIdx.x) >> 5;
    int lane = threadIdx.x & 31;
    if (warp >= N_NODES) return;
    int beg = g_rowptr[warp], end = g_rowptr[warp + 1];
    float ax = 0.f, ay = 0.f;
    int e = beg;
    for (; e + 4 <= end; e += 4) {
        int s0 = g_csr[e], s1 = g_csr[e + 1], s2 = g_csr[e + 2], s3 = g_csr[e + 3];
        uint32_t q0 = *(const uint32_t*)(yl + (size_t)s0 * 64 + lane * 2);
        uint32_t q1 = *(const uint32_t*)(yl + (size_t)s1 * 64 + lane * 2);
        uint32_t q2 = *(const uint32_t*)(yl + (size_t)s2 * 64 + lane * 2);
        uint32_t q3 = *(const uint32_t*)(yl + (size_t)s3 * 64 + lane * 2);
        float2 a0 = __half22float2(*(__half2*)&q0);
        float2 a1 = __half22float2(*(__half2*)&q1);
        float2 a2 = __half22float2(*(__half2*)&q2);
        float2 a3 = __half22float2(*(__half2*)&q3);
        ax += a0.x + a1.x + a2.x + a3.x;
        ay += a0.y + a1.y + a2.y + a3.y;
    }
    for (; e < end; e++) {
        int s = g_csr[e];
        uint32_t q = *(const uint32_t*)(yl + (size_t)s * 64 + lane * 2);
        float2 a = __half22float2(*(__half2*)&q);
        ax += a.x; ay += a.y;
    }
    int deg = end - beg;
    float inv = 1.f / (float)(deg > 0 ? deg : 1);
    float2 r = *(const float2*)(yr + (size_t)warp * 64 + lane * 2);
    float2 b = *(const float2*)(bias + lane * 2);
    float v0 = ax * inv + r.x + b.x;
    float v1 = ay * inv + r.y + b.y;
    *(float2*)(outPre + (size_t)warp * 64 + lane * 2) = make_float2(v0, v1);
}

// ====================== host launch =========================================
extern "C" void kernel_launch(void* const* d_in, const int* in_sizes, int n_in,
                              void* d_out, int out_size) {
    const float* x   = (const float*)d_in[0];
    const int*   ei  = (const int*)d_in[1];
    const float* Wl0 = (const float*)d_in[2];
    const float* Wr0 = (const float*)d_in[3];
    const float* b0  = (const float*)d_in[4];
    const float* Wl1 = (const float*)d_in[5];
    const float* Wr1 = (const float*)d_in[6];
    const float* b1  = (const float*)d_in[7];
    const float* Wl2 = (const float*)d_in[8];
    const float* Wr2 = (const float*)d_in[9];
    const float* b2  = (const float*)d_in[10];

    const int* src = ei;
    const int* dst = ei + N_EDGES;

    float* out_final = (float*)d_out;                       // [N,64]
    float* out_pre1  = out_final + (size_t)N_NODES * 64;    // [N,128] pre-relu layer1
    float* out_g     = out_pre1 + (size_t)N_NODES * 128;    // [N,128] relu(layer1)

    __half *ylhA, *ylhB, *actp; float *yrA, *yrB, *wt0, *wt1, *wt2;
    cudaGetSymbolAddress((void**)&ylhA, g_ylhA);
    cudaGetSymbolAddress((void**)&ylhB, g_ylhB);
    cudaGetSymbolAddress((void**)&yrA, g_yrA);
    cudaGetSymbolAddress((void**)&yrB, g_yrB);
    cudaGetSymbolAddress((void**)&actp, g_act);
    cudaGetSymbolAddress((void**)&wt0, g_wt0);
    cudaGetSymbolAddress((void**)&wt1, g_wt1);
    cudaGetSymbolAddress((void**)&wt2, g_wt2);

    static cudaStream_t s_side = nullptr, s_gemm = nullptr;
    static cudaEvent_t evFork = nullptr, evJoin = nullptr;
    static cudaEvent_t evA[NCHUNKS], evB[NCHUNKS], evG1 = nullptr, evG2 = nullptr;
    if (s_side == nullptr) {
        cudaStreamCreateWithFlags(&s_side, cudaStreamNonBlocking);
        cudaStreamCreateWithFlags(&s_gemm, cudaStreamNonBlocking);
        cudaEventCreateWithFlags(&evFork, cudaEventDisableTiming);
        cudaEventCreateWithFlags(&evJoin, cudaEventDisableTiming);
        cudaEventCreateWithFlags(&evG1, cudaEventDisableTiming);
        cudaEventCreateWithFlags(&evG2, cudaEventDisableTiming);
        for (int c = 0; c < NCHUNKS; c++) {
            cudaEventCreateWithFlags(&evA[c], cudaEventDisableTiming);
            cudaEventCreateWithFlags(&evB[c], cudaEventDisableTiming);
        }
    }

    // ---- fork: CSR build on side stream ----
    cudaEventRecord(evFork, 0);
    cudaStreamWaitEvent(s_side, evFork, 0);
    cudaStreamWaitEvent(s_gemm, evFork, 0);
    zero_kernel<<<(N_NODES + 1023) / 1024, 1024, 0, s_side>>>();
    deg_kernel<<<(N_EDGES + 255) / 256, 256, 0, s_side>>>(dst);
    scan1_kernel<<<SCAN_BLOCKS, 1024, 0, s_side>>>();
    scan2_kernel<<<1, 128, 0, s_side>>>();
    scan3_kernel<<<SCAN_BLOCKS, 1024, 0, s_side>>>();
    fill_kernel<<<(N_EDGES + 255) / 256, 256, 0, s_side>>>(src, dst);
    cudaEventRecord(evJoin, s_side);

    // ---- main stream overlaps the CSR build ----
    wtrans_kernel<<<(256 * 256 + 255) / 256, 256>>>(Wl0, Wr0, Wl1, Wr1, Wl2, Wr2);

    const int gemmGridX = (N_NODES + 127) / 128;   // 782

    // Layer 0 GEMM -> set A (full)
    gemm_mma_kernel<256, 256, float><<<dim3(gemmGridX, 2), 256>>>(x, wt0, ylhA, yrA, N_NODES);
    cudaStreamWaitEvent(0, evJoin, 0);   // agg needs the CSR

    // ---- pipelined: agg0 chunk c reads set A -> GEMM1 chunk c writes set B ----
    for (int c = 0; c < NCHUNKS; c++) {
        int cs = c * CHUNK;
        int mc = (cs + CHUNK <= N_NODES) ? CHUNK : (N_NODES - cs);
        agg128_kernel<false, false, true><<<(mc * 32 + 255) / 256, 256>>>(
            ylhA, yrA, b0, nullptr, nullptr, actp, cs, mc);
        cudaEventRecord(evA[c], 0);
        cudaStreamWaitEvent(s_gemm, evA[c], 0);
        gemm_mma_kernel<128, 256, __half><<<dim3((mc + 127) / 128, 2), 256, 0, s_gemm>>>(
            actp + (size_t)cs * 128, wt1, ylhB + (size_t)cs * 128, yrB + (size_t)cs * 128, mc);
    }
    cudaEventRecord(evG1, s_gemm);
    cudaStreamWaitEvent(0, evG1, 0);

    // ---- pipelined: agg1 chunk c reads set B -> GEMM2 chunk c writes set A ----
    // Set A is dead here: all agg0 chunks completed before evG1.
    for (int c = 0; c < NCHUNKS; c++) {
        int cs = c * CHUNK;
        int mc = (cs + CHUNK <= N_NODES) ? CHUNK : (N_NODES - cs);
        agg128_kernel<true, true, true><<<(mc * 32 + 255) / 256, 256>>>(
            ylhB, yrB, b1, out_pre1, out_g, actp, cs, mc);
        cudaEventRecord(evB[c], 0);
        cudaStreamWaitEvent(s_gemm, evB[c], 0);
        gemm_mma_kernel<128, 128, __half><<<dim3((mc + 127) / 128, 1), 256, 0, s_gemm>>>(
            actp + (size_t)cs * 128, wt2, ylhA + (size_t)cs * 64, yrA + (size_t)cs * 64, mc);
    }
    cudaEventRecord(evG2, s_gemm);
    cudaStreamWaitEvent(0, evG2, 0);

    // Layer 2 aggregation: x_final = mean(yl) + yr + b2 (reads set A, full)
    agg64_kernel<<<(N_NODES * 32 + 255) / 256, 256>>>(ylhA, yrA, b2, out_final);
}

// round 17
// speedup vs baseline: 1.1851x; 1.1509x over previous
#include <cuda_runtime.h>
#include <cuda_fp16.h>
#include <cstdint>

#define N_NODES 100000
#define N_EDGES 1600000
#define SCAN_BLOCKS 98   // ceil(100000/1024)

// ====================== helpers =============================================
__device__ __forceinline__ void mma_f16(float c[4], const uint32_t a[4], const uint32_t b[2]) {
    asm volatile(
        "mma.sync.aligned.m16n8k16.row.col.f32.f16.f16.f32 "
        "{%0,%1,%2,%3}, {%4,%5,%6,%7}, {%8,%9}, {%0,%1,%2,%3};"
        : "+f"(c[0]), "+f"(c[1]), "+f"(c[2]), "+f"(c[3])
        : "r"(a[0]), "r"(a[1]), "r"(a[2]), "r"(a[3]), "r"(b[0]), "r"(b[1]));
}
__device__ __forceinline__ uint32_t pack_h2(float a, float b) {
    __half2 h = __floats2half2_rn(a, b);
    return *(uint32_t*)&h;
}

// ====================== scratch globals =====================================
__device__ __half g_ylh[(size_t)N_NODES * 128];  // yl (fp16, gathered side)
__device__ float  g_yr[(size_t)N_NODES * 128];   // yr (fp32, exact side)
__device__ __half g_act[(size_t)N_NODES * 128];  // fp16 activations (h1 / g)
__device__ int    g_deg[N_NODES];
__device__ int    g_fill[N_NODES];
__device__ int    g_rowptr[N_NODES + 1];
__device__ int    g_csr[N_EDGES];
__device__ int    g_bsums[SCAN_BLOCKS];
__device__ float  g_wt0[256 * 256];   // [n][k]: n<128 -> Wl0[:,n], else Wr0[:,n-128]
__device__ float  g_wt1[256 * 128];
__device__ float  g_wt2[128 * 128];

// ====================== CSR build ===========================================
__global__ void zero_kernel() {
    int i = blockIdx.x * blockDim.x + threadIdx.x;
    if (i < N_NODES) { g_deg[i] = 0; g_fill[i] = 0; }
}
__global__ void deg_kernel(const int* __restrict__ dst) {
    int e = blockIdx.x * blockDim.x + threadIdx.x;
    if (e < N_EDGES) atomicAdd(&g_deg[dst[e]], 1);
}
__global__ void scan1_kernel() {
    __shared__ int s[1024];
    int tid = threadIdx.x;
    int idx = blockIdx.x * 1024 + tid;
    int v = (idx < N_NODES) ? g_deg[idx] : 0;
    s[tid] = v;
    __syncthreads();
    for (int off = 1; off < 1024; off <<= 1) {
        int t = 0;
        if (tid >= off) t = s[tid - off];
        __syncthreads();
        s[tid] += t;
        __syncthreads();
    }
    if (idx < N_NODES) g_rowptr[idx + 1] = s[tid];
    if (tid == 1023) g_bsums[blockIdx.x] = s[tid];
    if (idx == 0) g_rowptr[0] = 0;
}
__global__ void scan2_kernel() {       // 128-thread shfl scan over SCAN_BLOCKS sums
    int tid = threadIdx.x;
    int v = (tid < SCAN_BLOCKS) ? g_bsums[tid] : 0;
    int lane = tid & 31, w = tid >> 5;
    int x = v;
    for (int o = 1; o < 32; o <<= 1) {
        int t = __shfl_up_sync(0xFFFFFFFFu, x, o);
        if (lane >= o) x += t;
    }
    __shared__ int ws[4];
    if (lane == 31) ws[w] = x;
    __syncthreads();
    int add = 0;
    for (int i = 0; i < w; i++) add += ws[i];
    if (tid < SCAN_BLOCKS) g_bsums[tid] = x + add - v;  // exclusive
}
__global__ void scan3_kernel() {
    int idx = blockIdx.x * 1024 + threadIdx.x;
    if (idx < N_NODES) g_rowptr[idx + 1] += g_bsums[blockIdx.x];
}
__global__ void fill_kernel(const int* __restrict__ src, const int* __restrict__ dst) {
    int e = blockIdx.x * blockDim.x + threadIdx.x;
    if (e < N_EDGES) {
        int d = dst[e];
        int pos = g_rowptr[d] + atomicAdd(&g_fill[d], 1);
        g_csr[pos] = src[e];
    }
}

// ====================== weight pre-transpose ================================
__global__ void wtrans_kernel(const float* __restrict__ Wl0, const float* __restrict__ Wr0,
                              const float* __restrict__ Wl1, const float* __restrict__ Wr1,
                              const float* __restrict__ Wl2, const float* __restrict__ Wr2) {
    int i = blockIdx.x * blockDim.x + threadIdx.x;
    if (i < 256 * 256) {                       // wt0: N=256, K=256
        int n = i >> 8, k = i & 255;
        g_wt0[i] = (n < 128) ? Wl0[k * 128 + n] : Wr0[k * 128 + (n - 128)];
    }
    if (i < 256 * 128) {                       // wt1: N=256, K=128
        int n = i >> 7, k = i & 127;
        g_wt1[i] = (n < 128) ? Wl1[k * 128 + n] : Wr1[k * 128 + (n - 128)];
    }
    if (i < 128 * 128) {                       // wt2: N=128, K=128
        int n = i >> 7, k = i & 127;
        g_wt2[i] = (n < 64) ? Wl2[k * 64 + n] : Wr2[k * 64 + (n - 64)];
    }
}

// ====================== mma.sync fp16 GEMM (R10 proven) =====================
// Y[M, NN] = A[M, KT] * BT[NN, KT]^T, cols [0,SPLIT) -> fp16 ylh, rest -> fp32 yr.
#define KC 32
#define SH 40                              // halves per row; rows hit distinct banks
#define BUF_H (128 * SH)
#define STAGE_H (2 * BUF_H)

template <int KT, int NN, typename TA>
__global__ void __launch_bounds__(256)
gemm_mma_kernel(const TA* __restrict__ A, const float* __restrict__ BT,
                __half* __restrict__ ylh, float* __restrict__ yr, int M) {
    constexpr int SPLIT = NN / 2;
    constexpr bool A_IS_HALF = sizeof(TA) == 2;
    __shared__ __half sm[2 * STAGE_H];     // 40960 bytes
    const int tid = threadIdx.x;
    const int wid = tid >> 5;
    const int lane = tid & 31;
    const int warpM = wid & 3;
    const int warpN = wid >> 2;
    const int rowBase = blockIdx.x * 128;
    const int colBase = blockIdx.y * 128;
    constexpr int NC = KT / KC;

    float acc[2][8][4];
#pragma unroll
    for (int mt = 0; mt < 2; mt++)
#pragma unroll
        for (int nt = 0; nt < 8; nt++)
#pragma unroll
            for (int q = 0; q < 4; q++) acc[mt][nt][q] = 0.f;

    const int ldRow = tid >> 3;          // 0..31 (+i*32)
    const int ldKq  = (tid & 7) * 4;     // k offset (elements)

    uint2 ha[4];       // fp16 A path
    float4 ra[4];      // fp32 A path
    float4 rb[4];

    auto loadA = [&](int kBase) {
#pragma unroll
        for (int i = 0; i < 4; i++) {
            int gr = rowBase + ldRow + i * 32;
            if (A_IS_HALF) {
                ha[i] = (gr < M) ? *(const uint2*)((const __half*)A + (size_t)gr * KT + kBase + ldKq)
                                 : make_uint2(0u, 0u);
            } else {
                ra[i] = (gr < M) ? *(const float4*)((const float*)A + (size_t)gr * KT + kBase + ldKq)
                                 : make_float4(0.f, 0.f, 0.f, 0.f);
            }
        }
    };
    auto loadB = [&](int kBase) {
#pragma unroll
        for (int i = 0; i < 4; i++)
            rb[i] = *(const float4*)(BT + (size_t)(colBase + ldRow + i * 32) * KT + kBase + ldKq);
    };
    auto storeStage = [&](int stg) {
        __half* As = sm + stg * STAGE_H;
        __half* Bs = As + BUF_H;
#pragma unroll
        for (int i = 0; i < 4; i++) {
            int r = ldRow + i * 32;
            if (A_IS_HALF) {
                *(uint2*)(As + r * SH + ldKq) = ha[i];
            } else {
                *(uint2*)(As + r * SH + ldKq) = make_uint2(pack_h2(ra[i].x, ra[i].y),
                                                           pack_h2(ra[i].z, ra[i].w));
            }
            *(uint2*)(Bs + r * SH + ldKq) = make_uint2(pack_h2(rb[i].x, rb[i].y),
                                                       pack_h2(rb[i].z, rb[i].w));
        }
    };

    loadA(0); loadB(0); storeStage(0);
    __syncthreads();

    const int aRowB = warpM * 32 + (lane >> 2);
    const int aCol2 = (lane & 3) * 2;
    const int bRowB = warpN * 64 + (lane >> 2);

    for (int c = 0; c < NC; c++) {
        if (c + 1 < NC) { loadA((c + 1) * KC); loadB((c + 1) * KC); }
        const __half* As = sm + (c & 1) * STAGE_H;
        const __half* Bs = As + BUF_H;
#pragma unroll
        for (int ks = 0; ks < KC / 16; ks++) {
            const int k0 = ks * 16 + aCol2;
            uint32_t af[2][4];
            uint32_t bf[8][2];
#pragma unroll
            for (int mt = 0; mt < 2; mt++) {
                const __half* p = As + (aRowB + mt * 16) * SH + k0;
                af[mt][0] = *(const uint32_t*)(p);
                af[mt][1] = *(const uint32_t*)(p + 8 * SH);
                af[mt][2] = *(const uint32_t*)(p + 8);
                af[mt][3] = *(const uint32_t*)(p + 8 * SH + 8);
            }
#pragma unroll
            for (int nt = 0; nt < 8; nt++) {
                const __half* p = Bs + (bRowB + nt * 8) * SH + k0;
                bf[nt][0] = *(const uint32_t*)(p);
                bf[nt][1] = *(const uint32_t*)(p + 8);
            }
#pragma unroll
            for (int mt = 0; mt < 2; mt++)
#pragma unroll
                for (int nt = 0; nt < 8; nt++)
                    mma_f16(acc[mt][nt], af[mt], bf[nt]);
        }
        if (c + 1 < NC) {
            storeStage((c + 1) & 1);
            __syncthreads();
        }
    }

    // ---- epilogue: split write (fp16 yl / fp32 yr) ----
#pragma unroll
    for (int mt = 0; mt < 2; mt++) {
        int r0 = rowBase + warpM * 32 + mt * 16 + (lane >> 2);
#pragma unroll
        for (int nt = 0; nt < 8; nt++) {
            int colg = colBase + warpN * 64 + nt * 8 + (lane & 3) * 2;
#pragma unroll
            for (int hf = 0; hf < 2; hf++) {
                int row = r0 + hf * 8;
                if (row >= M) continue;
                float c0 = acc[mt][nt][hf * 2 + 0];
                float c1 = acc[mt][nt][hf * 2 + 1];
                if (colg < SPLIT) {
                    *(__half2*)(ylh + (size_t)row * SPLIT + colg) = __floats2half2_rn(c0, c1);
                } else {
                    *(float2*)(yr + (size_t)row * SPLIT + (colg - SPLIT)) = make_float2(c0, c1);
                }
            }
        }
    }
}

// ====================== aggregation epilogue ================================
// R10 structure; 128-thread blocks; gather unrolled to 8 edges/iteration.
template <bool WPRE32, bool WPOST32, bool WPOST16>
__global__ void agg128_kernel(const __half* __restrict__ yl, const float* __restrict__ yr,
                              const float* __restrict__ bias,
                              float* __restrict__ outPre, float* __restrict__ outPost,
                              __half* __restrict__ outPost16) {
    int warp = (blockIdx.x * blockDim.x + threadIdx.x) >> 5;
    int lane = threadIdx.x & 31;
    if (warp >= N_NODES) return;
    int beg = g_rowptr[warp], end = g_rowptr[warp + 1];
    float ax = 0.f, ay = 0.f, az = 0.f, aw = 0.f;
    int e = beg;
    for (; e + 8 <= end; e += 8) {
        int s0 = g_csr[e],     s1 = g_csr[e + 1], s2 = g_csr[e + 2], s3 = g_csr[e + 3];
        int s4 = g_csr[e + 4], s5 = g_csr[e + 5], s6 = g_csr[e + 6], s7 = g_csr[e + 7];
        uint2 q0 = *(const uint2*)(yl + (size_t)s0 * 128 + lane * 4);
        uint2 q1 = *(const uint2*)(yl + (size_t)s1 * 128 + lane * 4);
        uint2 q2 = *(const uint2*)(yl + (size_t)s2 * 128 + lane * 4);
        uint2 q3 = *(const uint2*)(yl + (size_t)s3 * 128 + lane * 4);
        uint2 q4 = *(const uint2*)(yl + (size_t)s4 * 128 + lane * 4);
        uint2 q5 = *(const uint2*)(yl + (size_t)s5 * 128 + lane * 4);
        uint2 q6 = *(const uint2*)(yl + (size_t)s6 * 128 + lane * 4);
        uint2 q7 = *(const uint2*)(yl + (size_t)s7 * 128 + lane * 4);
        float2 a0 = __half22float2(*(__half2*)&q0.x), b0 = __half22float2(*(__half2*)&q0.y);
        float2 a1 = __half22float2(*(__half2*)&q1.x), b1 = __half22float2(*(__half2*)&q1.y);
        float2 a2 = __half22float2(*(__half2*)&q2.x), b2 = __half22float2(*(__half2*)&q2.y);
        float2 a3 = __half22float2(*(__half2*)&q3.x), b3 = __half22float2(*(__half2*)&q3.y);
        float2 a4 = __half22float2(*(__half2*)&q4.x), b4 = __half22float2(*(__half2*)&q4.y);
        float2 a5 = __half22float2(*(__half2*)&q5.x), b5 = __half22float2(*(__half2*)&q5.y);
        float2 a6 = __half22float2(*(__half2*)&q6.x), b6 = __half22float2(*(__half2*)&q6.y);
        float2 a7 = __half22float2(*(__half2*)&q7.x), b7 = __half22float2(*(__half2*)&q7.y);
        ax += (a0.x + a1.x + a2.x + a3.x) + (a4.x + a5.x + a6.x + a7.x);
        ay += (a0.y + a1.y + a2.y + a3.y) + (a4.y + a5.y + a6.y + a7.y);
        az += (b0.x + b1.x + b2.x + b3.x) + (b4.x + b5.x + b6.x + b7.x);
        aw += (b0.y + b1.y + b2.y + b3.y) + (b4.y + b5.y + b6.y + b7.y);
    }
    for (; e + 4 <= end; e += 4) {
        int s0 = g_csr[e], s1 = g_csr[e + 1], s2 = g_csr[e + 2], s3 = g_csr[e + 3];
        uint2 q0 = *(const uint2*)(yl + (size_t)s0 * 128 + lane * 4);
        uint2 q1 = *(const uint2*)(yl + (size_t)s1 * 128 + lane * 4);
        uint2 q2 = *(const uint2*)(yl + (size_t)s2 * 128 + lane * 4);
        uint2 q3 = *(const uint2*)(yl + (size_t)s3 * 128 + lane * 4);
        float2 a0 = __half22float2(*(__half2*)&q0.x), b0 = __half22float2(*(__half2*)&q0.y);
        float2 a1 = __half22float2(*(__half2*)&q1.x), b1 = __half22float2(*(__half2*)&q1.y);
        float2 a2 = __half22float2(*(__half2*)&q2.x), b2 = __half22float2(*(__half2*)&q2.y);
        float2 a3 = __half22float2(*(__half2*)&q3.x), b3 = __half22float2(*(__half2*)&q3.y);
        ax += a0.x + a1.x + a2.x + a3.x;
        ay += a0.y + a1.y + a2.y + a3.y;
        az += b0.x + b1.x + b2.x + b3.x;
        aw += b0.y + b1.y + b2.y + b3.y;
    }
    for (; e < end; e++) {
        int s = g_csr[e];
        uint2 q = *(const uint2*)(yl + (size_t)s * 128 + lane * 4);
        float2 a = __half22float2(*(__half2*)&q.x), b = __half22float2(*(__half2*)&q.y);
        ax += a.x; ay += a.y; az += b.x; aw += b.y;
    }
    int deg = end - beg;
    float inv = 1.f / (float)(deg > 0 ? deg : 1);
    float4 r = *(const float4*)(yr + (size_t)warp * 128 + lane * 4);
    float4 b = *(const float4*)(bias + lane * 4);
    float v0 = ax * inv + r.x + b.x;
    float v1 = ay * inv + r.y + b.y;
    float v2 = az * inv + r.z + b.z;
    float v3 = aw * inv + r.w + b.w;
    size_t o = (size_t)warp * 128 + lane * 4;
    if (WPRE32)  *(float4*)(outPre + o) = make_float4(v0, v1, v2, v3);
    float p0 = fmaxf(v0, 0.f), p1 = fmaxf(v1, 0.f), p2 = fmaxf(v2, 0.f), p3 = fmaxf(v3, 0.f);
    if (WPOST32) *(float4*)(outPost + o) = make_float4(p0, p1, p2, p3);
    if (WPOST16) *(uint2*)(outPost16 + o) = make_uint2(pack_h2(p0, p1), pack_h2(p2, p3));
}

__global__ void agg64_kernel(const __half* __restrict__ yl, const float* __restrict__ yr,
                             const float* __restrict__ bias, float* __restrict__ outPre) {
    int warp = (blockIdx.x * blockDim.x + threadIdx.x) >> 5;
    int lane = threadIdx.x & 31;
    if (warp >= N_NODES) return;
    int beg = g_rowptr[warp], end = g_rowptr[warp + 1];
    float ax = 0.f, ay = 0.f;
    int e = beg;
    for (; e + 8 <= end; e += 8) {
        int s0 = g_csr[e],     s1 = g_csr[e + 1], s2 = g_csr[e + 2], s3 = g_csr[e + 3];
        int s4 = g_csr[e + 4], s5 = g_csr[e + 5], s6 = g_csr[e + 6], s7 = g_csr[e + 7];
        uint32_t q0 = *(const uint32_t*)(yl + (size_t)s0 * 64 + lane * 2);
        uint32_t q1 = *(const uint32_t*)(yl + (size_t)s1 * 64 + lane * 2);
        uint32_t q2 = *(const uint32_t*)(yl + (size_t)s2 * 64 + lane * 2);
        uint32_t q3 = *(const uint32_t*)(yl + (size_t)s3 * 64 + lane * 2);
        uint32_t q4 = *(const uint32_t*)(yl + (size_t)s4 * 64 + lane * 2);
        uint32_t q5 = *(const uint32_t*)(yl + (size_t)s5 * 64 + lane * 2);
        uint32_t q6 = *(const uint32_t*)(yl + (size_t)s6 * 64 + lane * 2);
        uint32_t q7 = *(const uint32_t*)(yl + (size_t)s7 * 64 + lane * 2);
        float2 a0 = __half22float2(*(__half2*)&q0);
        float2 a1 = __half22float2(*(__half2*)&q1);
        float2 a2 = __half22float2(*(__half2*)&q2);
        float2 a3 = __half22float2(*(__half2*)&q3);
        float2 a4 = __half22float2(*(__half2*)&q4);
        float2 a5 = __half22float2(*(__half2*)&q5);
        float2 a6 = __half22float2(*(__half2*)&q6);
        float2 a7 = __half22float2(*(__half2*)&q7);
        ax += (a0.x + a1.x + a2.x + a3.x) + (a4.x + a5.x + a6.x + a7.x);
        ay += (a0.y + a1.y + a2.y + a3.y) + (a4.y + a5.y + a6.y + a7.y);
    }
    for (; e + 4 <= end; e += 4) {
        int s0 = g_csr[e], s1 = g_csr[e + 1], s2 = g_csr[e + 2], s3 = g_csr[e + 3];
        uint32_t q0 = *(const uint32_t*)(yl + (size_t)s0 * 64 + lane * 2);
        uint32_t q1 = *(const uint32_t*)(yl + (size_t)s1 * 64 + lane * 2);
        uint32_t q2 = *(const uint32_t*)(yl + (size_t)s2 * 64 + lane * 2);
        uint32_t q3 = *(const uint32_t*)(yl + (size_t)s3 * 64 + lane * 2);
        float2 a0 = __half22float2(*(__half2*)&q0);
        float2 a1 = __half22float2(*(__half2*)&q1);
        float2 a2 = __half22float2(*(__half2*)&q2);
        float2 a3 = __half22float2(*(__half2*)&q3);
        ax += a0.x + a1.x + a2.x + a3.x;
        ay += a0.y + a1.y + a2.y + a3.y;
    }
    for (; e < end; e++) {
        int s = g_csr[e];
        uint32_t q = *(const uint32_t*)(yl + (size_t)s * 64 + lane * 2);
        float2 a = __half22float2(*(__half2*)&q);
        ax += a.x; ay += a.y;
    }
    int deg = end - beg;
    float inv = 1.f / (float)(deg > 0 ? deg : 1);
    float2 r = *(const float2*)(yr + (size_t)warp * 64 + lane * 2);
    float2 b = *(const float2*)(bias + lane * 2);
    float v0 = ax * inv + r.x + b.x;
    float v1 = ay * inv + r.y + b.y;
    *(float2*)(outPre + (size_t)warp * 64 + lane * 2) = make_float2(v0, v1);
}

// ====================== host launch =========================================
extern "C" void kernel_launch(void* const* d_in, const int* in_sizes, int n_in,
                              void* d_out, int out_size) {
    const float* x   = (const float*)d_in[0];
    const int*   ei  = (const int*)d_in[1];
    const float* Wl0 = (const float*)d_in[2];
    const float* Wr0 = (const float*)d_in[3];
    const float* b0  = (const float*)d_in[4];
    const float* Wl1 = (const float*)d_in[5];
    const float* Wr1 = (const float*)d_in[6];
    const float* b1  = (const float*)d_in[7];
    const float* Wl2 = (const float*)d_in[8];
    const float* Wr2 = (const float*)d_in[9];
    const float* b2  = (const float*)d_in[10];

    const int* src = ei;
    const int* dst = ei + N_EDGES;

    float* out_final = (float*)d_out;                       // [N,64]
    float* out_pre1  = out_final + (size_t)N_NODES * 64;    // [N,128] pre-relu layer1
    float* out_g     = out_pre1 + (size_t)N_NODES * 128;    // [N,128] relu(layer1)

    __half *ylh, *actp; float *yrp, *wt0, *wt1, *wt2;
    cudaGetSymbolAddress((void**)&ylh, g_ylh);
    cudaGetSymbolAddress((void**)&actp, g_act);
    cudaGetSymbolAddress((void**)&yrp, g_yr);
    cudaGetSymbolAddress((void**)&wt0, g_wt0);
    cudaGetSymbolAddress((void**)&wt1, g_wt1);
    cudaGetSymbolAddress((void**)&wt2, g_wt2);

    static cudaStream_t s_side = nullptr;
    static cudaEvent_t evFork = nullptr, evJoin = nullptr;
    if (s_side == nullptr) {
        cudaStreamCreateWithFlags(&s_side, cudaStreamNonBlocking);
        cudaEventCreateWithFlags(&evFork, cudaEventDisableTiming);
        cudaEventCreateWithFlags(&evJoin, cudaEventDisableTiming);
    }

    // ---- fork: CSR build on side stream ----
    cudaEventRecord(evFork, 0);
    cudaStreamWaitEvent(s_side, evFork, 0);
    zero_kernel<<<(N_NODES + 1023) / 1024, 1024, 0, s_side>>>();
    deg_kernel<<<(N_EDGES + 255) / 256, 256, 0, s_side>>>(dst);
    scan1_kernel<<<SCAN_BLOCKS, 1024, 0, s_side>>>();
    scan2_kernel<<<1, 128, 0, s_side>>>();
    scan3_kernel<<<SCAN_BLOCKS, 1024, 0, s_side>>>();
    fill_kernel<<<(N_EDGES + 255) / 256, 256, 0, s_side>>>(src, dst);
    cudaEventRecord(evJoin, s_side);

    // ---- main stream overlaps the CSR build ----
    wtrans_kernel<<<(256 * 256 + 255) / 256, 256>>>(Wl0, Wr0, Wl1, Wr1, Wl2, Wr2);

    const int aggGrid = (N_NODES * 32 + 127) / 128;   // 128-thread blocks (4 warps)
    const int gemmGridX = (N_NODES + 127) / 128;      // 782

    // Layer 0: [yl|yr] = x@[Wl0|Wr0]; h1(fp16) = relu(mean(yl) + yr + b0)
    gemm_mma_kernel<256, 256, float><<<dim3(gemmGridX, 2), 256>>>(x, wt0, ylh, yrp, N_NODES);
    cudaStreamWaitEvent(0, evJoin, 0);   // agg needs the CSR
    agg128_kernel<false, false, true><<<aggGrid, 128>>>(ylh, yrp, b0, nullptr, nullptr, actp);

    // Layer 1: out_pre1 = mean+yr+b1; g -> out_g (fp32) + g_act (fp16)
    gemm_mma_kernel<128, 256, __half><<<dim3(gemmGridX, 2), 256>>>(actp, wt1, ylh, yrp, N_NODES);
    agg128_kernel<true, true, true><<<aggGrid, 128>>>(ylh, yrp, b1, out_pre1, out_g, actp);

    // Layer 2: x_final = mean(yl) + yr + b2 (no relu)
    gemm_mma_kernel<128, 128, __half><<<dim3(gemmGridX, 1), 256>>>(actp, wt2, ylh, yrp, N_NODES);
    agg64_kernel<<<aggGrid, 128>>>(ylh, yrp, b2, out_final);
}